// round 9
// baseline (speedup 1.0000x reference)
#include <cuda_runtime.h>
#include <cuda_bf16.h>
#include <math.h>

// Problem constants (fixed shapes from the reference)
constexpr int B_   = 16;
constexpr int T_   = 64;
constexpr int HWC  = 32 * 32 * 64;   // 65536 elements per (b, t) slab
constexpr int PV   = HWC / 4;        // float4 vectors per slab = 16384
constexpr int BH   = B_ / 2;         // batches per half = 8
constexpr int NTHR = BH * PV;        // total threads = 131072

__global__ __launch_bounds__(256)
void alif2d_kernel(const float4* __restrict__ x,        // [B, T, HWC/4]
                   const float*  __restrict__ hp_base_step,
                   const float*  __restrict__ hp_base_decay,
                   const float4* __restrict__ step_w_raw, // [HWC/4]
                   const float4* __restrict__ decay_w_raw,
                   const float4* __restrict__ gamma,
                   const float4* __restrict__ beta,
                   float4* __restrict__ out_s,            // [B, T, HWC/4]
                   float4* __restrict__ out_v)            // [B, T, HWC/4]
{
    const int idx = blockIdx.x * blockDim.x + threadIdx.x;   // grid is exact

    const int p = idx & (PV - 1);     // position within HWC slab (vec units)
    const int b = idx >> 14;          // idx / PV, in [0, 8)

    const float bs = __ldg(hp_base_step);
    const float bd = __ldg(hp_base_decay);

    const float4 swr = step_w_raw[p];
    const float4 dwr = decay_w_raw[p];
    const float4 g4  = gamma[p];
    const float4 be4 = beta[p];

    float g[4]   = {g4.x, g4.y, g4.z, g4.w};
    float be[4]  = {be4.x, be4.y, be4.z, be4.w};
    float swra[4]= {swr.x, swr.y, swr.z, swr.w};
    float dwra[4]= {dwr.x, dwr.y, dwr.z, dwr.w};

    float step_eff[4], decay_eff[4];
#pragma unroll
    for (int i = 0; i < 4; i++) {
        // softplus(x) = log1p(exp(x)); sigmoid(x) = 1/(1+exp(-x))
        float sp  = log1pf(expf(swra[i]));
        float sig = 1.0f / (1.0f + expf(-dwra[i]));
        step_eff[i]  = bs * sp;
        decay_eff[i] = bd + (1.0f - bd) * sig;
    }

    // Two independent recurrences: batch b and batch b+8, same position p
    float va[4]   = {0.f, 0.f, 0.f, 0.f};
    float vtha[4] = {0.f, 0.f, 0.f, 0.f};
    float vb[4]   = {0.f, 0.f, 0.f, 0.f};
    float vthb[4] = {0.f, 0.f, 0.f, 0.f};

    const size_t offA = (size_t)b * T_ * PV + p;
    const size_t offB = (size_t)(b + BH) * T_ * PV + p;

    const float4* xpa = x     + offA;
    float4*       spa = out_s + offA;
    float4*       vpa = out_v + offA;
    const float4* xpb = x     + offB;
    float4*       spb = out_s + offB;
    float4*       vpb = out_v + offB;

#pragma unroll 2
    for (int t = 0; t < T_; t++) {
        const size_t o = (size_t)t * PV;
        // Two independent 128-bit loads in flight together
        const float4 xva = __ldg(xpa + o);
        const float4 xvb = __ldg(xpb + o);

        float xa[4] = {xva.x, xva.y, xva.z, xva.w};
        float xbv[4] = {xvb.x, xvb.y, xvb.z, xvb.w};

        float sa[4], voa[4], sb[4], vob[4];
#pragma unroll
        for (int i = 0; i < 4; i++) {
            // recurrence A
            float vi = fmaf(va[i], 0.8f, fmaf(xa[i], g[i], be[i]));
            float vth_eff = 0.5f + vtha[i];
            float s = (vi - vth_eff > 0.0f) ? 1.0f : 0.0f;
            voa[i] = vi;
            sa[i]  = s;
            va[i]  = vi - vth_eff * s;
            vtha[i] = fmaf(vtha[i], decay_eff[i], s * step_eff[i]);
            // recurrence B
            float vj = fmaf(vb[i], 0.8f, fmaf(xbv[i], g[i], be[i]));
            float vth_effb = 0.5f + vthb[i];
            float sB = (vj - vth_effb > 0.0f) ? 1.0f : 0.0f;
            vob[i] = vj;
            sb[i]  = sB;
            vb[i]  = vj - vth_effb * sB;
            vthb[i] = fmaf(vthb[i], decay_eff[i], sB * step_eff[i]);
        }

        spa[o] = make_float4(sa[0], sa[1], sa[2], sa[3]);
        vpa[o] = make_float4(voa[0], voa[1], voa[2], voa[3]);
        spb[o] = make_float4(sb[0], sb[1], sb[2], sb[3]);
        vpb[o] = make_float4(vob[0], vob[1], vob[2], vob[3]);
    }
}

extern "C" void kernel_launch(void* const* d_in, const int* in_sizes, int n_in,
                              void* d_out, int out_size)
{
    // metadata order: x, hp_alpha, hp_base_step, hp_base_decay,
    //                 step_w_raw, decay_w_raw, gamma, beta
    const float4* x    = (const float4*)d_in[0];
    // d_in[1] = hp_alpha (unused in forward pass)
    const float*  hbs  = (const float*)d_in[2];
    const float*  hbd  = (const float*)d_in[3];
    const float4* swr  = (const float4*)d_in[4];
    const float4* dwr  = (const float4*)d_in[5];
    const float4* gam  = (const float4*)d_in[6];
    const float4* bet  = (const float4*)d_in[7];

    const size_t n_per = (size_t)B_ * T_ * HWC;   // 67,108,864 elements
    float4* out_s = (float4*)d_out;
    float4* out_v = (float4*)((float*)d_out + n_per);

    const int threads = 256;
    const int blocks  = NTHR / threads;   // 512, exact
    alif2d_kernel<<<blocks, threads>>>(x, hbs, hbd, swr, dwr, gam, bet,
                                       out_s, out_v);
}

// round 10
// speedup vs baseline: 1.1345x; 1.1345x over previous
#include <cuda_runtime.h>
#include <cuda_bf16.h>
#include <math.h>

// Problem constants (fixed shapes from the reference)
constexpr int B_   = 16;
constexpr int T_   = 64;
constexpr int HWC  = 32 * 32 * 64;   // 65536 elements per (b, t) slab
constexpr int PV2  = HWC / 2;        // float2 vectors per slab = 32768
constexpr int NTHR = B_ * PV2;       // total threads = 524288

// Dynamic smem pad: limits occupancy to exactly 5 CTAs/SM (227KB / 40KB = 5)
// so that N/C = 524288 / (148*5*256) = 2.768 -> utilization 92.3%.
// 6 CTAs/SM would give ratio 2.31 -> 77% (worse than current 86.5%).
constexpr int SMEM_PAD = 40960;

__global__ __launch_bounds__(256, 5)
void alif2d_kernel(const float2* __restrict__ x,        // [B, T, HWC/2]
                   const float*  __restrict__ hp_base_step,
                   const float*  __restrict__ hp_base_decay,
                   const float2* __restrict__ step_w_raw, // [HWC/2]
                   const float2* __restrict__ decay_w_raw,
                   const float2* __restrict__ gamma,
                   const float2* __restrict__ beta,
                   float2* __restrict__ out_s,            // [B, T, HWC/2]
                   float2* __restrict__ out_v)            // [B, T, HWC/2]
{
    extern __shared__ char _pad[];   // occupancy limiter only
    (void)_pad;

    const int idx = blockIdx.x * blockDim.x + threadIdx.x;   // grid exact

    const int p = idx & (PV2 - 1);    // position within HWC slab (vec units)
    const int b = idx >> 15;          // idx / PV2  (PV2 = 32768 = 2^15)

    const float bs = __ldg(hp_base_step);
    const float bd = __ldg(hp_base_decay);

    const float2 swr = step_w_raw[p];
    const float2 dwr = decay_w_raw[p];
    const float2 g2  = gamma[p];
    const float2 be2 = beta[p];

    float g[2]  = {g2.x, g2.y};
    float be[2] = {be2.x, be2.y};

    float step_eff[2], decay_eff[2];
    {
        float swra[2] = {swr.x, swr.y};
        float dwra[2] = {dwr.x, dwr.y};
#pragma unroll
        for (int i = 0; i < 2; i++) {
            // softplus(x) = log1p(exp(x)); sigmoid(x) = 1/(1+exp(-x))
            float sp  = log1pf(expf(swra[i]));
            float sig = 1.0f / (1.0f + expf(-dwra[i]));
            step_eff[i]  = bs * sp;
            decay_eff[i] = bd + (1.0f - bd) * sig;
        }
    }

    float v[2]   = {0.f, 0.f};
    float vth[2] = {0.f, 0.f};

    const float2* xp = x     + (size_t)b * T_ * PV2 + p;
    float2*       sp = out_s + (size_t)b * T_ * PV2 + p;
    float2*       vp = out_v + (size_t)b * T_ * PV2 + p;

#pragma unroll 4
    for (int t = 0; t < T_; t++) {
        const float2 xv = __ldg(xp + (size_t)t * PV2);
        float xa[2] = {xv.x, xv.y};

        float s_out[2], v_out[2];
#pragma unroll
        for (int i = 0; i < 2; i++) {
            // v = v*0.8 + (x*gamma + beta)
            float vi = fmaf(v[i], 0.8f, fmaf(xa[i], g[i], be[i]));
            float vth_eff = 0.5f + vth[i];
            float s = (vi - vth_eff > 0.0f) ? 1.0f : 0.0f;
            v_out[i] = vi;            // voltages output is pre-reset v
            s_out[i] = s;
            v[i]   = vi - vth_eff * s;
            vth[i] = fmaf(vth[i], decay_eff[i], s * step_eff[i]);
        }

        sp[(size_t)t * PV2] = make_float2(s_out[0], s_out[1]);
        vp[(size_t)t * PV2] = make_float2(v_out[0], v_out[1]);
    }
}

extern "C" void kernel_launch(void* const* d_in, const int* in_sizes, int n_in,
                              void* d_out, int out_size)
{
    // metadata order: x, hp_alpha, hp_base_step, hp_base_decay,
    //                 step_w_raw, decay_w_raw, gamma, beta
    const float2* x    = (const float2*)d_in[0];
    // d_in[1] = hp_alpha (unused in forward pass)
    const float*  hbs  = (const float*)d_in[2];
    const float*  hbd  = (const float*)d_in[3];
    const float2* swr  = (const float2*)d_in[4];
    const float2* dwr  = (const float2*)d_in[5];
    const float2* gam  = (const float2*)d_in[6];
    const float2* bet  = (const float2*)d_in[7];

    const size_t n_per = (size_t)B_ * T_ * HWC;   // 67,108,864 elements
    float2* out_s = (float2*)d_out;
    float2* out_v = (float2*)((float*)d_out + n_per);

    const int threads = 256;
    const int blocks  = NTHR / threads;   // 2048, exact
    alif2d_kernel<<<blocks, threads, SMEM_PAD>>>(x, hbs, hbd, swr, dwr, gam, bet,
                                                 out_s, out_v);
}

// round 11
// speedup vs baseline: 1.2330x; 1.0868x over previous
#include <cuda_runtime.h>
#include <cuda_bf16.h>
#include <math.h>

// Problem constants (fixed shapes from the reference)
constexpr int B_   = 16;
constexpr int T_   = 64;
constexpr int HWC  = 32 * 32 * 64;   // 65536 elements per (b, t) slab
constexpr int PV2  = HWC / 2;        // float2 vectors per slab = 32768
constexpr int NTHR = B_ * PV2;       // total threads = 524288

// Occupancy shaping WITHOUT a smem pad: the kernel compiles to 46 regs
// (verified in R10), and 65536 regs/SM / (46*256) = 5.56 -> 5 CTAs/SM from
// registers alone. N/C = 524288 / (148*5*256) = 2.768 -> 92.3% wave util
// (vs 86.5% for the float4/4-CTA R1 shape), with the full 228KB L1D intact
// (R10's 40KB dynamic-smem pad cut L1D to ~28KB and cost 8 points of DRAM%).

__global__ __launch_bounds__(256, 5)
void alif2d_kernel(const float2* __restrict__ x,        // [B, T, HWC/2]
                   const float*  __restrict__ hp_base_step,
                   const float*  __restrict__ hp_base_decay,
                   const float2* __restrict__ step_w_raw, // [HWC/2]
                   const float2* __restrict__ decay_w_raw,
                   const float2* __restrict__ gamma,
                   const float2* __restrict__ beta,
                   float2* __restrict__ out_s,            // [B, T, HWC/2]
                   float2* __restrict__ out_v)            // [B, T, HWC/2]
{
    const int idx = blockIdx.x * blockDim.x + threadIdx.x;   // grid exact

    const int p = idx & (PV2 - 1);    // position within HWC slab (vec units)
    const int b = idx >> 15;          // idx / PV2  (PV2 = 32768 = 2^15)

    const float bs = __ldg(hp_base_step);
    const float bd = __ldg(hp_base_decay);

    const float2 swr = step_w_raw[p];
    const float2 dwr = decay_w_raw[p];
    const float2 g2  = gamma[p];
    const float2 be2 = beta[p];

    float g[2]  = {g2.x, g2.y};
    float be[2] = {be2.x, be2.y};

    float step_eff[2], decay_eff[2];
    {
        float swra[2] = {swr.x, swr.y};
        float dwra[2] = {dwr.x, dwr.y};
#pragma unroll
        for (int i = 0; i < 2; i++) {
            // softplus(x) = log1p(exp(x)); sigmoid(x) = 1/(1+exp(-x))
            float sp  = log1pf(expf(swra[i]));
            float sig = 1.0f / (1.0f + expf(-dwra[i]));
            step_eff[i]  = bs * sp;
            decay_eff[i] = bd + (1.0f - bd) * sig;
        }
    }

    float v[2]   = {0.f, 0.f};
    float vth[2] = {0.f, 0.f};

    const float2* xp = x     + (size_t)b * T_ * PV2 + p;
    float2*       sp = out_s + (size_t)b * T_ * PV2 + p;
    float2*       vp = out_v + (size_t)b * T_ * PV2 + p;

#pragma unroll 4
    for (int t = 0; t < T_; t++) {
        const float2 xv = __ldg(xp + (size_t)t * PV2);
        float xa[2] = {xv.x, xv.y};

        float s_out[2], v_out[2];
#pragma unroll
        for (int i = 0; i < 2; i++) {
            // v = v*0.8 + (x*gamma + beta)
            float vi = fmaf(v[i], 0.8f, fmaf(xa[i], g[i], be[i]));
            float vth_eff = 0.5f + vth[i];
            float s = (vi - vth_eff > 0.0f) ? 1.0f : 0.0f;
            v_out[i] = vi;            // voltages output is pre-reset v
            s_out[i] = s;
            v[i]   = vi - vth_eff * s;
            vth[i] = fmaf(vth[i], decay_eff[i], s * step_eff[i]);
        }

        sp[(size_t)t * PV2] = make_float2(s_out[0], s_out[1]);
        vp[(size_t)t * PV2] = make_float2(v_out[0], v_out[1]);
    }
}

extern "C" void kernel_launch(void* const* d_in, const int* in_sizes, int n_in,
                              void* d_out, int out_size)
{
    // metadata order: x, hp_alpha, hp_base_step, hp_base_decay,
    //                 step_w_raw, decay_w_raw, gamma, beta
    const float2* x    = (const float2*)d_in[0];
    // d_in[1] = hp_alpha (unused in forward pass)
    const float*  hbs  = (const float*)d_in[2];
    const float*  hbd  = (const float*)d_in[3];
    const float2* swr  = (const float2*)d_in[4];
    const float2* dwr  = (const float2*)d_in[5];
    const float2* gam  = (const float2*)d_in[6];
    const float2* bet  = (const float2*)d_in[7];

    const size_t n_per = (size_t)B_ * T_ * HWC;   // 67,108,864 elements
    float2* out_s = (float2*)d_out;
    float2* out_v = (float2*)((float*)d_out + n_per);

    const int threads = 256;
    const int blocks  = NTHR / threads;   // 2048, exact
    alif2d_kernel<<<blocks, threads>>>(x, hbs, hbd, swr, dwr, gam, bet,
                                       out_s, out_v);
}